// round 17
// baseline (speedup 1.0000x reference)
#include <cuda_runtime.h>
#include <cuda_bf16.h>
#include <cuda_fp16.h>
#include <cstdint>

// Problem constants
#define B_  4
#define S_  2048
#define D_  1024
#define H_  16
#define HD_ 64
#define M_  (B_*S_)   // 8192
#define NKT 32        // 1024 / 32 k-tiles

#define CQ  0.1803368801111244f   // 0.125 * log2(e): folded into Q

// Scratch (device globals — no allocation allowed)
__device__ __half g_qh[(size_t)B_*H_*S_*HD_];   // Q*CQ  [B,H,S,64] fp16
__device__ __half g_kh[(size_t)B_*H_*S_*HD_];   // K     [B,H,S,64] fp16
__device__ __half g_vt[(size_t)B_*H_*80*S_];    // V^T [B,H,80,S]; row64=1, 65..79=0
__device__ __half g_xh[(size_t)M_*D_];          // x fp16
__device__ __half g_ctxh[(size_t)M_*D_];        // ctx fp16
__device__ __half g_wh[4][(size_t)D_*D_];       // Wq,Wk,Wv,Wo fp16

// ---------------------------------------------------------------------------
// PTX helpers
// ---------------------------------------------------------------------------
__device__ __forceinline__ void cp_async16(uint32_t s, const void* g) {
    asm volatile("cp.async.cg.shared.global [%0], [%1], 16;\n" :: "r"(s), "l"(g));
}
__device__ __forceinline__ void cp_commit() {
    asm volatile("cp.async.commit_group;\n");
}
__device__ __forceinline__ void ldsm_x4(uint32_t* r, uint32_t addr) {
    asm volatile("ldmatrix.sync.aligned.m8n8.x4.shared.b16 {%0,%1,%2,%3}, [%4];\n"
        : "=r"(r[0]), "=r"(r[1]), "=r"(r[2]), "=r"(r[3]) : "r"(addr));
}
__device__ __forceinline__ void mma_f16(float* c, const uint32_t* a, const uint32_t* b) {
    asm volatile("mma.sync.aligned.m16n8k16.row.col.f32.f16.f16.f32 "
        "{%0,%1,%2,%3}, {%4,%5,%6,%7}, {%8,%9}, {%0,%1,%2,%3};\n"
        : "+f"(c[0]), "+f"(c[1]), "+f"(c[2]), "+f"(c[3])
        : "r"(a[0]), "r"(a[1]), "r"(a[2]), "r"(a[3]), "r"(b[0]), "r"(b[1]));
}
__device__ __forceinline__ float ex2f(float x) {
    float r;
    asm("ex2.approx.ftz.f32 %0, %1;" : "=f"(r) : "f"(x));
    return r;
}
__device__ __forceinline__ uint32_t packh2(float a, float b) {
    __half2 h = __floats2half2_rn(a, b);
    return *(uint32_t*)&h;
}

// ---------------------------------------------------------------------------
// Fused prep: x->fp16, W*->fp16, V^T pad init. Flat grid, 256 threads.
// blocks [0,8192): x   [8192,12288): W (1024 each)   [12288,13312): vt pad
// ---------------------------------------------------------------------------
__device__ __forceinline__ ushort4 cvt4(float4 v) {
    return make_ushort4(__half_as_ushort(__float2half_rn(v.x)),
                        __half_as_ushort(__float2half_rn(v.y)),
                        __half_as_ushort(__float2half_rn(v.z)),
                        __half_as_ushort(__float2half_rn(v.w)));
}

__global__ __launch_bounds__(256) void prep_kernel(
    const float4* __restrict__ x4,
    const float4* __restrict__ Wq4, const float4* __restrict__ Wk4,
    const float4* __restrict__ Wv4, const float4* __restrict__ Wo4)
{
    int bx = blockIdx.x;
    if (bx < 8192) {
        int i = bx * 256 + threadIdx.x;
        *(ushort4*)&g_xh[(size_t)i * 4] = cvt4(x4[i]);
    } else if (bx < 12288) {
        int r = bx - 8192;
        int which = r >> 10;
        const float4* src = (which == 0) ? Wq4 : (which == 1) ? Wk4
                          : (which == 2) ? Wv4 : Wo4;
        int i = (r & 1023) * 256 + threadIdx.x;
        *(ushort4*)&g_wh[which][(size_t)i * 4] = cvt4(src[i]);
    } else {
        // vt pad rows 64..79: chunk = 8 halves
        int c = (bx - 12288) * 256 + threadIdx.x;   // 0..262143
        int bh  = c >> 12;
        int rem = c & 4095;
        int r   = rem >> 8;          // 0..15 -> row 64+r
        int s8  = (rem & 255) * 8;
        uint32_t w = (r == 0) ? 0x3C003C00u : 0u;   // half(1.0) pair or 0
        uint4 val = make_uint4(w, w, w, w);
        *(uint4*)&g_vt[((size_t)bh * 80 + 64 + r) * S_ + s8] = val;
    }
}

// ---------------------------------------------------------------------------
// fp16 MMA GEMM: CTA tile 128x256, warp tile 64x64 (8 warps, 2m x 4n).
// K=1024, 4-stage cp.async, one barrier per stage. 1 CTA/SM.
// ---------------------------------------------------------------------------
#define SPITCH  40                  // halves per smem row (32 data + 8 pad)
#define RSTRIDE (64*SPITCH*2)       // 5120 B per 64 rows
#define ST      4
#define STA_B   (128*SPITCH*2)      // 10240 B per A stage
#define STB_B   (256*SPITCH*2)      // 20480 B per B stage
#define GEMM_SMEM (ST*(STA_B+STB_B))// 122880 B

template<bool PERM>
__global__ __launch_bounds__(256, 1) void mma_gemm_kernel(float* __restrict__ outp)
{
    extern __shared__ __half dsm[];

    const __half* A;
    const __half* W;
    if (PERM) { A = g_xh;   W = g_wh[blockIdx.z]; }
    else      { A = g_ctxh; W = g_wh[3]; }

    const int tid  = threadIdx.x;
    const int lane = tid & 31;
    const int wid  = tid >> 5;
    const int wm   = wid & 1;     // 2 warps along M (64 rows each)
    const int wn   = wid >> 1;    // 4 warps along N (64 cols each)
    const int m0   = blockIdx.y * 128;
    const int n0   = blockIdx.x * 256;

    const int c0r = tid >> 2;           // 0..63
    const int c0c = (tid & 3) * 8;      // half offset

    const uint32_t aS = (uint32_t)__cvta_generic_to_shared(dsm);
    const uint32_t bS = aS + ST * STA_B;
    const uint32_t stA0 = aS + (uint32_t)(c0r * SPITCH + c0c) * 2;
    const uint32_t stB0 = bS + (uint32_t)(c0r * SPITCH + c0c) * 2;

    const int a_row = wm * 64 + (lane & 15);
    const int a_k   = (lane >> 4) * 8;
    const int b_row = wn * 64 + (lane & 7) + ((lane & 16) ? 8 : 0);
    const int b_k   = (lane & 8) ? 8 : 0;

    float acc[4][8][4];
#pragma unroll
    for (int mi = 0; mi < 4; ++mi)
#pragma unroll
        for (int ni = 0; ni < 8; ++ni)
#pragma unroll
            for (int r = 0; r < 4; ++r) acc[mi][ni][r] = 0.0f;

    auto issue = [&](int kt, int buf) {
        int koff = kt * 32;
        uint32_t sa = stA0 + (uint32_t)buf * STA_B;
        uint32_t sb = stB0 + (uint32_t)buf * STB_B;
        cp_async16(sa,           A + (size_t)(m0 + c0r) * D_ + koff + c0c);
        cp_async16(sa + RSTRIDE, A + (size_t)(m0 + c0r + 64) * D_ + koff + c0c);
#pragma unroll
        for (int j = 0; j < 4; ++j)
            cp_async16(sb + (uint32_t)j * RSTRIDE,
                       W + (size_t)(n0 + c0r + j * 64) * D_ + koff + c0c);
        cp_commit();
    };

    issue(0, 0);
    issue(1, 1);
    issue(2, 2);

    for (int kt = 0; kt < NKT; ++kt) {
        const int cur = kt & 3;
        if (kt < NKT - 2)      asm volatile("cp.async.wait_group 2;\n");
        else if (kt == NKT-2)  asm volatile("cp.async.wait_group 1;\n");
        else                   asm volatile("cp.async.wait_group 0;\n");
        __syncthreads();   // publishes stage cur; orders reads of stage (kt-1)&3

        if (kt + 3 < NKT) issue(kt + 3, (kt + 3) & 3);

        const uint32_t smA_cur = aS + (uint32_t)cur * STA_B;
        const uint32_t smB_cur = bS + (uint32_t)cur * STB_B;
#pragma unroll
        for (int kk = 0; kk < 32; kk += 16) {
            uint32_t af[4][4], bfr[4][4];
#pragma unroll
            for (int mi = 0; mi < 4; ++mi)
                ldsm_x4(af[mi], smA_cur + ((a_row + mi * 16) * SPITCH + kk + a_k) * 2);
#pragma unroll
            for (int np = 0; np < 4; ++np)
                ldsm_x4(bfr[np], smB_cur + ((b_row + np * 16) * SPITCH + kk + b_k) * 2);
#pragma unroll
            for (int mi = 0; mi < 4; ++mi)
#pragma unroll
                for (int ni = 0; ni < 8; ++ni)
                    mma_f16(acc[mi][ni], af[mi], &bfr[ni >> 1][(ni & 1) * 2]);
        }
    }

    // Epilogue
    const int tr = lane >> 2;
    const int tc = (lane & 3) * 2;
#pragma unroll
    for (int mi = 0; mi < 4; ++mi) {
#pragma unroll
        for (int ni = 0; ni < 8; ++ni) {
            int r = m0 + wm * 64 + mi * 16 + tr;
            int c = n0 + wn * 64 + ni * 8 + tc;
#pragma unroll
            for (int half_ = 0; half_ < 2; ++half_) {
                int m = r + half_ * 8;
                float v0 = acc[mi][ni][half_ * 2 + 0];
                float v1 = acc[mi][ni][half_ * 2 + 1];
                if (PERM) {
                    int b  = m >> 11;
                    int s  = m & (S_ - 1);
                    int hh = c >> 6;
                    int hd = c & 63;
                    size_t bh = (size_t)(b * H_ + hh);
                    if (blockIdx.z == 2) {
                        size_t base = (bh * 80 + hd) * S_ + s;
                        g_vt[base]      = __float2half_rn(v0);
                        g_vt[base + S_] = __float2half_rn(v1);
                    } else {
                        __half* dh = (blockIdx.z == 0) ? g_qh : g_kh;
                        if (blockIdx.z == 0) { v0 *= CQ; v1 *= CQ; }
                        size_t idx = (bh * S_ + s) * 64 + hd;
                        *(__half2*)&dh[idx] = __floats2half2_rn(v0, v1);
                    }
                } else {
                    *(float2*)&outp[(size_t)m * D_ + c] = make_float2(v0, v1);
                }
            }
        }
    }
}

// ---------------------------------------------------------------------------
// MMA flash attention (unchanged from R16 — verified).
// ---------------------------------------------------------------------------
#define PITCH 72
#define Q_O   0
#define ST_H  (144*PITCH)                  // halves per K/V stage
#define K_OFF(b) (128*PITCH + (b)*ST_H)
#define V_OFF(b) (K_OFF(b) + 64*PITCH)
#define SM_HALVES (128*PITCH + 2*ST_H)     // 29952 halves = 59904 B

__global__ __launch_bounds__(256, 2) void attn_mma_kernel()
{
    extern __shared__ __half sm[];
    const uint32_t sbase = (uint32_t)__cvta_generic_to_shared(sm);

    const int bh  = blockIdx.x;
    const int qt  = 15 - blockIdx.y;      // heavy tiles first
    const int q0  = qt * 128;
    const int tid = threadIdx.x;
    const int lane = tid & 31;
    const int wq   = tid >> 5;

    const __half* gQh = g_qh + (size_t)bh * S_ * 64;
    const __half* gKh = g_kh + (size_t)bh * S_ * 64;
    const __half* gVt = g_vt + (size_t)bh * 80 * S_;

    for (int i = tid; i < 128 * 8; i += 256) {
        int r = i >> 3, ch = (i & 7) * 8;
        *(float4*)&sm[Q_O + r * PITCH + ch] = *(const float4*)&gQh[(size_t)(q0 + r) * 64 + ch];
    }

    const int lr = tid >> 3;
    const int lc = (tid & 7) * 8;
    auto issue_kv = [&](int kt, int buf) {
        uint32_t kb = sbase + (uint32_t)(K_OFF(buf)) * 2;
        uint32_t vb = sbase + (uint32_t)(V_OFF(buf)) * 2;
#pragma unroll
        for (int j = 0; j < 2; ++j) {
            int r = lr + j * 32;
            cp_async16(kb + (uint32_t)(r * PITCH + lc) * 2,
                       gKh + (size_t)(kt * 64 + r) * 64 + lc);
        }
#pragma unroll
        for (int j = 0; j < 3; ++j) {
            int r = lr + j * 32;
            if (r < 80)
                cp_async16(vb + (uint32_t)(r * PITCH + lc) * 2,
                           gVt + (size_t)r * S_ + kt * 64 + lc);
        }
        cp_commit();
    };

    float O[10][4];
#pragma unroll
    for (int f = 0; f < 10; ++f)
#pragma unroll
        for (int r = 0; r < 4; ++r) O[f][r] = 0.0f;
    float m0r = -1e30f, m1r = -1e30f;

    const int row0 = q0 + wq * 16 + (lane >> 2);
    const int row1 = row0 + 8;
    const int ccol = (lane & 3) * 2;

    const uint32_t aoff = ((wq * 16 + (lane & 15)) * PITCH + (lane >> 4) * 8) * 2;
    const int brow = (lane & 7) + ((lane & 16) ? 8 : 0);
    const int bk   = (lane & 8) ? 8 : 0;

    const int nkt = 2 * qt + 2;
    issue_kv(0, 0);
    for (int kt = 0; kt < nkt; ++kt) {
        const int cur = kt & 1;
        asm volatile("cp.async.wait_group 0;\n");
        __syncthreads();
        if (kt + 1 < nkt) issue_kv(kt + 1, cur ^ 1);

        if (kt * 64 > q0 + wq * 16 + 15) continue;

        const uint32_t kS = sbase + (uint32_t)(K_OFF(cur)) * 2;
        const uint32_t vS = sbase + (uint32_t)(V_OFF(cur)) * 2;

        float S[8][4];
#pragma unroll
        for (int j = 0; j < 8; ++j)
#pragma unroll
            for (int r = 0; r < 4; ++r) S[j][r] = 0.0f;

#pragma unroll
        for (int kc = 0; kc < 4; ++kc) {
            uint32_t ah[4];
            ldsm_x4(ah, sbase + (Q_O)*2 + aoff + kc * 32);
#pragma unroll
            for (int np = 0; np < 4; ++np) {
                uint32_t bhf[4];
                ldsm_x4(bhf, kS + (uint32_t)(((np * 16 + brow) * PITCH + kc * 16 + bk) * 2));
                mma_f16(S[np * 2 + 0], ah, &bhf[0]);
                mma_f16(S[np * 2 + 1], ah, &bhf[2]);
            }
        }

        if (kt * 64 + 63 > q0 + wq * 16) {
#pragma unroll
            for (int j = 0; j < 8; ++j) {
                int c0 = kt * 64 + j * 8 + ccol;
                if (c0     > row0) S[j][0] = -30000.0f;
                if (c0 + 1 > row0) S[j][1] = -30000.0f;
                if (c0     > row1) S[j][2] = -30000.0f;
                if (c0 + 1 > row1) S[j][3] = -30000.0f;
            }
        }

        float mt0 = -1e30f, mt1 = -1e30f;
#pragma unroll
        for (int j = 0; j < 8; ++j) {
            mt0 = fmaxf(mt0, fmaxf(S[j][0], S[j][1]));
            mt1 = fmaxf(mt1, fmaxf(S[j][2], S[j][3]));
        }
#pragma unroll
        for (int off = 1; off <= 2; off <<= 1) {
            mt0 = fmaxf(mt0, __shfl_xor_sync(0xffffffffu, mt0, off));
            mt1 = fmaxf(mt1, __shfl_xor_sync(0xffffffffu, mt1, off));
        }
        float mn0 = fmaxf(m0r, mt0), mn1 = fmaxf(m1r, mt1);
        float a0 = ex2f(m0r - mn0), a1 = ex2f(m1r - mn1);
        m0r = mn0; m1r = mn1;
#pragma unroll
        for (int f = 0; f < 10; ++f) {
            O[f][0] *= a0; O[f][1] *= a0;
            O[f][2] *= a1; O[f][3] *= a1;
        }

        uint32_t ap[4][4];
#pragma unroll
        for (int kc = 0; kc < 4; ++kc) {
            int j0 = 2 * kc, j1 = 2 * kc + 1;
            ap[kc][0] = packh2(ex2f(S[j0][0] - mn0), ex2f(S[j0][1] - mn0));
            ap[kc][1] = packh2(ex2f(S[j0][2] - mn1), ex2f(S[j0][3] - mn1));
            ap[kc][2] = packh2(ex2f(S[j1][0] - mn0), ex2f(S[j1][1] - mn0));
            ap[kc][3] = packh2(ex2f(S[j1][2] - mn1), ex2f(S[j1][3] - mn1));
        }

#pragma unroll
        for (int kc = 0; kc < 4; ++kc) {
#pragma unroll
            for (int np = 0; np < 5; ++np) {
                uint32_t bv[4];
                ldsm_x4(bv, vS + (uint32_t)(((np * 16 + brow) * PITCH + kc * 16 + bk) * 2));
                mma_f16(O[np * 2 + 0], ap[kc], &bv[0]);
                mma_f16(O[np * 2 + 1], ap[kc], &bv[2]);
            }
        }
    }

    float l0 = __shfl_sync(0xffffffffu, O[8][0], lane & ~3);
    float l1 = __shfl_sync(0xffffffffu, O[8][2], lane & ~3);
    float i0 = 1.0f / l0, i1 = 1.0f / l1;
    const int b = bh >> 4, h = bh & 15;
#pragma unroll
    for (int j = 0; j < 8; ++j) {
        int c = h * 64 + j * 8 + ccol;
#pragma unroll
        for (int half_ = 0; half_ < 2; ++half_) {
            int srow = half_ ? row1 : row0;
            float v0 = O[j][half_ * 2 + 0] * (half_ ? i1 : i0);
            float v1 = O[j][half_ * 2 + 1] * (half_ ? i1 : i0);
            *(__half2*)&g_ctxh[((size_t)b * S_ + srow) * D_ + c] =
                __floats2half2_rn(v0, v1);
        }
    }
}

// ---------------------------------------------------------------------------
// Launch
// ---------------------------------------------------------------------------
extern "C" void kernel_launch(void* const* d_in, const int* in_sizes, int n_in,
                              void* d_out, int out_size)
{
    const float* x  = (const float*)d_in[0];
    const float* Wq = (const float*)d_in[1];
    const float* Wk = (const float*)d_in[2];
    const float* Wv = (const float*)d_in[3];
    const float* Wo = (const float*)d_in[4];
    float* out = (float*)d_out;

    // 0) fused prep (x/W converts + V^T pad init)
    prep_kernel<<<13312, 256>>>((const float4*)x, (const float4*)Wq,
                                (const float4*)Wk, (const float4*)Wv,
                                (const float4*)Wo);

    // 1) QKV projections (fp16 MMA, 128x256 tiles) -> fp16 attention operands
    {
        cudaFuncSetAttribute(mma_gemm_kernel<true>,
                             cudaFuncAttributeMaxDynamicSharedMemorySize, GEMM_SMEM);
        dim3 grid(D_ / 256, M_ / 128, 3);
        mma_gemm_kernel<true><<<grid, 256, GEMM_SMEM>>>(nullptr);
    }

    // 2) MMA flash attention -> g_ctxh (fp16)
    {
        const int smem_bytes = SM_HALVES * 2;   // 59904
        cudaFuncSetAttribute(attn_mma_kernel,
                             cudaFuncAttributeMaxDynamicSharedMemorySize, smem_bytes);
        dim3 grid(B_ * H_, S_ / 128);
        attn_mma_kernel<<<grid, 256, smem_bytes>>>();
    }

    // 3) output projection -> d_out
    {
        cudaFuncSetAttribute(mma_gemm_kernel<false>,
                             cudaFuncAttributeMaxDynamicSharedMemorySize, GEMM_SMEM);
        dim3 grid(D_ / 256, M_ / 128);
        mma_gemm_kernel<false><<<grid, 256, GEMM_SMEM>>>(out);
    }
}